// round 15
// baseline (speedup 1.0000x reference)
#include <cuda_runtime.h>

#define B_DIM 8
#define H_DIM 8
#define P_DIM 4
#define PB 32
#define FEAT 64
#define EMB 32
#define HIN 96
#define GH 32
#define T_DIM 101770
#define TILE_T 64
#define JT 2
#define NUM_TILES ((T_DIM + TILE_T - 1) / TILE_T)   // 1591
#define ATT_STRIDE 100   // 96+4: per-phase conflict-free lane-strided LDS.128
#define GEN_STRIDE 36    // 32+4
#define GRID_MAIN 444    // 3 blocks per SM

// att double buffer: att weight tile only
#define ABUF_FLOATS (TILE_T * ATT_STRIDE)            // 6400
// gen single buffer: gen tile + hmid
#define OFF_HMID    (TILE_T * GEN_STRIDE)            // 2304
#define GBUF_FLOATS (OFF_HMID + PB * GH)             // 3328

// ---------------- device scratch ----------------
__device__ __align__(16) float g_h1[B_DIM * 128];
__device__ __align__(16) float g_hin[PB * HIN];
__device__ __align__(16) float g_hmid[H_DIM * PB * GH];
__device__ __align__(16) float g_gate[B_DIM * H_DIM];

// ---------------- helpers ----------------
static __device__ __forceinline__ unsigned long long ffma2(
    unsigned long long a, unsigned long long b, unsigned long long c) {
    unsigned long long d;
    asm("fma.rn.f32x2 %0, %1, %2, %3;" : "=l"(d) : "l"(a), "l"(b), "l"(c));
    return d;
}
static __device__ __forceinline__ float2 upk(unsigned long long a) {
    float2 f;
    asm("mov.b64 {%0, %1}, %2;" : "=f"(f.x), "=f"(f.y) : "l"(a));
    return f;
}
static __device__ __forceinline__ unsigned smem_u32(const void* p) {
    return (unsigned)__cvta_generic_to_shared(p);
}
#define CP16(dst, src) asm volatile("cp.async.cg.shared.global [%0], [%1], 16;" :: "r"(dst), "l"(src))
#define CP_COMMIT()    asm volatile("cp.async.commit_group;")
#define CP_WAIT0()     asm volatile("cp.async.wait_group 0;")

// ---------------- kA1: h1 = relu(x @ fe_W1^T + fe_b1), 64 blocks ---------
__global__ __launch_bounds__(128) void kA1(
    const float* __restrict__ x,
    const float* __restrict__ W1, const float* __restrict__ b1) {
    const int jc = blockIdx.x >> 3, b = blockIdx.x & 7;
    const int j = jc * 16 + (threadIdx.x >> 3), q = threadIdx.x & 7;
    const float2* xr = (const float2*)(x + b * 784) + q * 49;
    const float2* wr = (const float2*)(W1 + (size_t)j * 784) + q * 49;
    float s = 0.f;
#pragma unroll 7
    for (int i = 0; i < 49; i++) {
        float2 a = xr[i], w = wr[i];
        s += a.x * w.x + a.y * w.y;
    }
    s += __shfl_xor_sync(0xffffffffu, s, 1);
    s += __shfl_xor_sync(0xffffffffu, s, 2);
    s += __shfl_xor_sync(0xffffffffu, s, 4);
    if (q == 0) g_h1[b * 128 + j] = fmaxf(s + b1[j], 0.f);
}

// ---------------- kA2: feats, gate softmax, hin (8 blocks x 128) ---------
__global__ __launch_bounds__(128) void kA2(
    const float* __restrict__ fe_W2, const float* __restrict__ fe_b2,
    const float* __restrict__ embeds,
    const float* __restrict__ gateW, const float* __restrict__ gateB) {
    __shared__ float sh1[128];
    __shared__ float sfe[FEAT];
    __shared__ float slog[H_DIM];
    const int b = blockIdx.x, tid = threadIdx.x;

    sh1[tid] = g_h1[b * 128 + tid];
    __syncthreads();
    {   // feats[b][f]; 2 lanes per f
        const int f = tid >> 1, half = tid & 1;
        const float* w = fe_W2 + f * 128 + half * 64;
        const float* hh = sh1 + half * 64;
        float s = 0.f;
#pragma unroll 16
        for (int k = 0; k < 64; k++) s += hh[k] * w[k];
        s += __shfl_xor_sync(0xffffffffu, s, 1);
        if (half == 0) sfe[f] = s + fe_b2[f];
    }
    __syncthreads();
    if (tid < H_DIM) {
        float s = gateB[tid];
        for (int f = 0; f < FEAT; f++) s += sfe[f] * gateW[tid * FEAT + f];
        slog[tid] = s;
    }
    __syncthreads();
    if (tid < H_DIM) {
        float m = -1e30f;
        for (int h = 0; h < H_DIM; h++) m = fmaxf(m, slog[h]);
        float sum = 0.f;
        for (int h = 0; h < H_DIM; h++) sum += expf(slog[h] - m);
        g_gate[b * H_DIM + tid] = expf(slog[tid] - m) / sum;
    }
    for (int i = tid; i < P_DIM * HIN; i += 128) {
        int p = i / HIN, k = i % HIN;
        float v = (k < FEAT) ? sfe[k] : embeds[p * EMB + (k - FEAT)];
        g_hin[(p * B_DIM + b) * HIN + k] = v;
    }
}

// ---------------- kB: hmid = relu(hin @ gen_W1^T + gen_b1) ---------------
__global__ void kB(const float* __restrict__ W1,
                   const float* __restrict__ b1) {
    int idx = blockIdx.x * blockDim.x + threadIdx.x;    // 32 x 256
    int h = idx >> 10, r = idx & 1023, pb = r >> 5, j = r & 31;
    const float4* w = (const float4*)(W1 + (size_t)(h * GH + j) * HIN);
    const float4* hv = (const float4*)(g_hin + pb * HIN);
    float s = 0.f;
#pragma unroll
    for (int i = 0; i < HIN / 4; i++) {
        float4 a = hv[i], ww = w[i];
        s += a.x * ww.x + a.y * ww.y + a.z * ww.z + a.w * ww.w;
    }
    s += b1[h * GH + j];
    g_hmid[(h * PB + pb) * GH + j] = fmaxf(s, 0.f);
}

// ---------------- stage att weight tile (tile,h) via cp.async ------------
static __device__ __forceinline__ void stage_att(
    float* abuf, int tile, int h, int tid,
    const float* __restrict__ attW) {
    const int t0 = tile * TILE_T;
    const int nrow = min(TILE_T, T_DIM - t0);
    const unsigned uA = smem_u32(abuf);
    const float4* srcA = (const float4*)(attW + (size_t)(h * T_DIM + t0) * HIN);
    if (nrow == TILE_T) {
#pragma unroll
        for (int it = 0; it < 12; ++it) {               // 64*24 = 1536 f4
            int i = tid + it * 128;
            int r = i / (HIN / 4), c = i % (HIN / 4);
            CP16(uA + (unsigned)(r * ATT_STRIDE + c * 4) * 4u, srcA + i);
        }
    } else {
        int nA = nrow * (HIN / 4);
#pragma unroll
        for (int it = 0; it < 12; ++it) {
            int i = tid + it * 128;
            if (i < nA) {
                int r = i / (HIN / 4), c = i % (HIN / 4);
                CP16(uA + (unsigned)(r * ATT_STRIDE + c * 4) * 4u, srcA + i);
            }
        }
    }
}

// ---------------- stage gen+hmid (tile,h) into gen buffer ----------------
static __device__ __forceinline__ void stage_gen(
    float* gbuf, int tile, int h, int tid,
    const float* __restrict__ genW2) {
    const int t0 = tile * TILE_T;
    const int nrow = min(TILE_T, T_DIM - t0);
    const unsigned uG = smem_u32(gbuf);
    const unsigned uM = smem_u32(gbuf + OFF_HMID);
    const float4* srcG = (const float4*)(genW2 + (size_t)(h * T_DIM + t0) * GH);
    const float4* srcM = (const float4*)(g_hmid + h * PB * GH);
    CP16(uM + (unsigned)tid * 16u, srcM + tid);
    CP16(uM + (unsigned)(tid + 128) * 16u, srcM + tid + 128);
    if (nrow == TILE_T) {
#pragma unroll
        for (int it = 0; it < 4; ++it) {                // 64*8 = 512 f4
            int i = tid + it * 128;
            int r = i >> 3, c = i & 7;
            CP16(uG + (unsigned)(r * GEN_STRIDE + c * 4) * 4u, srcG + i);
        }
    } else {
        int nG = nrow * (GH / 4);
#pragma unroll
        for (int it = 0; it < 4; ++it) {
            int i = tid + it * 128;
            if (i < nG) {
                int r = i >> 3, c = i & 7;
                CP16(uG + (unsigned)(r * GEN_STRIDE + c * 4) * 4u, srcG + i);
            }
        }
    }
}

// ---------------- main fused kernel --------------------------------------
// 128 threads = 32 t-lanes x 4 pb-groups; thread owns 2 t x 8 pb.
// att double-buffered (prefetch at top); gen single-buffered (re-staged at
// mid sync); biases via predicated LDG. 3 blocks/SM = 12 warps (3/SMSP).
__global__ __launch_bounds__(128, 3) void k_main(
    const float* __restrict__ attW, const float* __restrict__ attB,
    const float* __restrict__ genW2, const float* __restrict__ genB2,
    float* __restrict__ out) {
    extern __shared__ float smem[];
    float* abufs[2] = { smem, smem + ABUF_FLOATS };
    float* gbuf  = smem + 2 * ABUF_FLOATS;
    float* sHin  = gbuf + GBUF_FLOATS;                   // 32*96
    float* sGate = sHin + PB * HIN;                      // 64

    const int tid = threadIdx.x;
    const int lane = tid & 31;                           // t-lane
    const int wpb = tid >> 5;                            // pb group 0..3
    const int bid = blockIdx.x;

    for (int i = tid; i < PB * HIN; i += 128) sHin[i] = g_hin[i];
    if (tid < B_DIM * H_DIM) sGate[tid] = g_gate[tid];

    const int ntile = (NUM_TILES - bid + GRID_MAIN - 1) / GRID_MAIN;
    const int nit = ntile * H_DIM;

    stage_att(abufs[0], bid, 0, tid, attW);
    stage_gen(gbuf, bid, 0, tid, genW2);
    CP_COMMIT();

    float comb[JT][8];

    for (int it = 0; it < nit; ++it) {
        const int cur = it & 1;
        const int h = it & 7;
        const int tile = bid + (it >> 3) * GRID_MAIN;
        const int t0 = tile * TILE_T;

        CP_WAIT0();
        __syncthreads();    // current att+gen landed; prev iter fully done

        // issue bias loads early (coalesced LDG, land before use)
        float gb[JT], ab[JT];
#pragma unroll
        for (int jt = 0; jt < JT; ++jt) {
            int t = t0 + lane + 32 * jt;
            bool v = t < T_DIM;
            gb[jt] = v ? __ldg(genB2 + (size_t)h * T_DIM + t) : 0.f;
            ab[jt] = v ? __ldg(attB + (size_t)h * T_DIM + t) : 0.f;
        }

        // prefetch next att NOW -> full iteration to land
        if (it + 1 < nit) {
            const int n2 = it + 1;
            stage_att(abufs[cur ^ 1], bid + (n2 >> 3) * GRID_MAIN, n2 & 7,
                      tid, attW);
        }
        CP_COMMIT();

        const float* sAtt  = abufs[cur];
        const float* sGen  = gbuf;
        const float* sHmid = gbuf + OFF_HMID;

        if (h == 0) {
#pragma unroll
            for (int jt = 0; jt < JT; ++jt)
#pragma unroll
                for (int j = 0; j < 8; ++j) comb[jt][j] = 0.f;
        }

        unsigned long long acc[JT][8];
#pragma unroll
        for (int jt = 0; jt < JT; ++jt)
#pragma unroll
            for (int j = 0; j < 8; ++j) acc[jt][j] = 0ull;

        // ---------- gen GEMM: hmid[h,pb,:] . genW2[h,t,:] ----------
#pragma unroll
        for (int k4 = 0; k4 < GH / 4; ++k4) {
            ulonglong2 w[JT];
#pragma unroll
            for (int jt = 0; jt < JT; ++jt)
                w[jt] = *(const ulonglong2*)&sGen[(lane + 32 * jt) * GEN_STRIDE + k4 * 4];
#pragma unroll
            for (int j = 0; j < 8; ++j) {
                ulonglong2 hv = *(const ulonglong2*)&sHmid[(wpb * 8 + j) * GH + k4 * 4];
#pragma unroll
                for (int jt = 0; jt < JT; ++jt) {
                    acc[jt][j] = ffma2(hv.x, w[jt].x, acc[jt][j]);
                    acc[jt][j] = ffma2(hv.y, w[jt].y, acc[jt][j]);
                }
            }
        }
        float gv[JT][8];
#pragma unroll
        for (int jt = 0; jt < JT; ++jt)
#pragma unroll
            for (int j = 0; j < 8; ++j) {
                float2 f = upk(acc[jt][j]);
                gv[jt][j] = f.x + f.y + gb[jt];
                acc[jt][j] = 0ull;
            }

        __syncthreads();    // everyone done reading gen buffer
        if (it + 1 < nit) { // prefetch next gen while att GEMM runs
            const int n2 = it + 1;
            stage_gen(gbuf, bid + (n2 >> 3) * GRID_MAIN, n2 & 7, tid, genW2);
        }
        CP_COMMIT();

        // ---------- att GEMM: hin[pb,:] . attW[h,t,:] ----------
#pragma unroll 4
        for (int k4 = 0; k4 < HIN / 4; ++k4) {
            ulonglong2 w[JT];
#pragma unroll
            for (int jt = 0; jt < JT; ++jt)
                w[jt] = *(const ulonglong2*)&sAtt[(lane + 32 * jt) * ATT_STRIDE + k4 * 4];
#pragma unroll
            for (int j = 0; j < 8; ++j) {
                ulonglong2 hv = *(const ulonglong2*)&sHin[(wpb * 8 + j) * HIN + k4 * 4];
#pragma unroll
                for (int jt = 0; jt < JT; ++jt) {
                    acc[jt][j] = ffma2(hv.x, w[jt].x, acc[jt][j]);
                    acc[jt][j] = ffma2(hv.y, w[jt].y, acc[jt][j]);
                }
            }
        }

        // ---------- sigmoid + gated combine: gate[h, b], b = j ----------
        float gt[8];
#pragma unroll
        for (int j = 0; j < 8; ++j) gt[j] = sGate[h * B_DIM + j];
#pragma unroll
        for (int jt = 0; jt < JT; ++jt)
#pragma unroll
            for (int j = 0; j < 8; ++j) {
                float2 f = upk(acc[jt][j]);
                float a = f.x + f.y + ab[jt];
                float imp = 1.0f / (1.0f + __expf(-a));
                comb[jt][j] = fmaf(gt[j] * gv[jt][j], imp, comb[jt][j]);
            }

        // ---------- store at last head (coalesced over lanes) ----------
        if (h == 7) {
#pragma unroll
            for (int jt = 0; jt < JT; ++jt) {
                int t = t0 + lane + 32 * jt;
                if (t < T_DIM) {
#pragma unroll
                    for (int j = 0; j < 8; ++j)
                        out[(size_t)(j * P_DIM + wpb) * T_DIM + t] = comb[jt][j];
                }
            }
        }
    }
}

// ---------------- launch ----------------
extern "C" void kernel_launch(void* const* d_in, const int* in_sizes, int n_in,
                              void* d_out, int out_size) {
    const float* x      = (const float*)d_in[0];
    const float* fe_W1  = (const float*)d_in[1];
    const float* fe_b1  = (const float*)d_in[2];
    const float* fe_W2  = (const float*)d_in[3];
    const float* fe_b2  = (const float*)d_in[4];
    const float* embeds = (const float*)d_in[5];
    const float* gen_W1 = (const float*)d_in[6];
    const float* gen_b1 = (const float*)d_in[7];
    const float* gen_W2 = (const float*)d_in[8];
    const float* gen_b2 = (const float*)d_in[9];
    const float* att_W  = (const float*)d_in[10];
    const float* att_b  = (const float*)d_in[11];
    const float* gate_W = (const float*)d_in[12];
    const float* gate_b = (const float*)d_in[13];
    float* out = (float*)d_out;

    size_t smem = (size_t)(2 * ABUF_FLOATS + GBUF_FLOATS +
                           PB * HIN + B_DIM * H_DIM) * sizeof(float);
    cudaFuncSetAttribute(k_main, cudaFuncAttributeMaxDynamicSharedMemorySize, (int)smem);

    kA1<<<64, 128>>>(x, fe_W1, fe_b1);
    kA2<<<B_DIM, 128>>>(fe_W2, fe_b2, embeds, gate_W, gate_b);
    kB<<<32, 256>>>(gen_W1, gen_b1);
    k_main<<<GRID_MAIN, 128, smem>>>(att_W, att_b, gen_W2, gen_b2, out);
}

// round 16
// speedup vs baseline: 1.3868x; 1.3868x over previous
#include <cuda_runtime.h>

#define B_DIM 8
#define H_DIM 8
#define P_DIM 4
#define PB 32
#define FEAT 64
#define EMB 32
#define HIN 96
#define GH 32
#define T_DIM 101770
#define TILE_T 64
#define JT 2
#define NUM_TILES ((T_DIM + TILE_T - 1) / TILE_T)   // 1591
#define ATT_STRIDE 100   // 96+4: lane-strided LDS.128 conflict-free (mod32==4)
#define GEN_STRIDE 36    // 32+4
#define GRID_MAIN 444    // 3 blocks per SM (one wave)

// att double buffer: att weight tile only
#define ABUF_FLOATS (TILE_T * ATT_STRIDE)            // 6400
// gen single buffer: gen tile + hmid
#define OFF_HMID    (TILE_T * GEN_STRIDE)            // 2304
#define GBUF_FLOATS (OFF_HMID + PB * GH)             // 3328
// total smem: 2*6400 + 3328 + 3072 = 19200 floats = 76800 B
// + 1024 B per-block reserve = 77824 B; x3 = 233472 B = 228 KB exactly.

// ---------------- device scratch ----------------
__device__ __align__(16) float g_h1[B_DIM * 128];
__device__ __align__(16) float g_hin[PB * HIN];
__device__ __align__(16) float g_hmid[H_DIM * PB * GH];
__device__ __align__(16) float g_gate[B_DIM * H_DIM];

// ---------------- helpers ----------------
static __device__ __forceinline__ unsigned long long ffma2(
    unsigned long long a, unsigned long long b, unsigned long long c) {
    unsigned long long d;
    asm("fma.rn.f32x2 %0, %1, %2, %3;" : "=l"(d) : "l"(a), "l"(b), "l"(c));
    return d;
}
static __device__ __forceinline__ float2 upk(unsigned long long a) {
    float2 f;
    asm("mov.b64 {%0, %1}, %2;" : "=f"(f.x), "=f"(f.y) : "l"(a));
    return f;
}
static __device__ __forceinline__ unsigned smem_u32(const void* p) {
    return (unsigned)__cvta_generic_to_shared(p);
}
#define CP16(dst, src) asm volatile("cp.async.cg.shared.global [%0], [%1], 16;" :: "r"(dst), "l"(src))
#define CP_COMMIT()    asm volatile("cp.async.commit_group;")
#define CP_WAIT0()     asm volatile("cp.async.wait_group 0;")

// ---------------- kA1: h1 = relu(x @ fe_W1^T + fe_b1), 64 blocks ---------
__global__ __launch_bounds__(128) void kA1(
    const float* __restrict__ x,
    const float* __restrict__ W1, const float* __restrict__ b1) {
    const int jc = blockIdx.x >> 3, b = blockIdx.x & 7;
    const int j = jc * 16 + (threadIdx.x >> 3), q = threadIdx.x & 7;
    const float2* xr = (const float2*)(x + b * 784) + q * 49;
    const float2* wr = (const float2*)(W1 + (size_t)j * 784) + q * 49;
    float s = 0.f;
#pragma unroll 7
    for (int i = 0; i < 49; i++) {
        float2 a = xr[i], w = wr[i];
        s += a.x * w.x + a.y * w.y;
    }
    s += __shfl_xor_sync(0xffffffffu, s, 1);
    s += __shfl_xor_sync(0xffffffffu, s, 2);
    s += __shfl_xor_sync(0xffffffffu, s, 4);
    if (q == 0) g_h1[b * 128 + j] = fmaxf(s + b1[j], 0.f);
}

// ---------------- kA2: feats, gate softmax, hin (8 blocks x 128) ---------
__global__ __launch_bounds__(128) void kA2(
    const float* __restrict__ fe_W2, const float* __restrict__ fe_b2,
    const float* __restrict__ embeds,
    const float* __restrict__ gateW, const float* __restrict__ gateB) {
    __shared__ float sh1[128];
    __shared__ float sfe[FEAT];
    __shared__ float slog[H_DIM];
    const int b = blockIdx.x, tid = threadIdx.x;

    sh1[tid] = g_h1[b * 128 + tid];
    __syncthreads();
    {   // feats[b][f]; 2 lanes per f
        const int f = tid >> 1, half = tid & 1;
        const float* w = fe_W2 + f * 128 + half * 64;
        const float* hh = sh1 + half * 64;
        float s = 0.f;
#pragma unroll 16
        for (int k = 0; k < 64; k++) s += hh[k] * w[k];
        s += __shfl_xor_sync(0xffffffffu, s, 1);
        if (half == 0) sfe[f] = s + fe_b2[f];
    }
    __syncthreads();
    if (tid < H_DIM) {
        float s = gateB[tid];
        for (int f = 0; f < FEAT; f++) s += sfe[f] * gateW[tid * FEAT + f];
        slog[tid] = s;
    }
    __syncthreads();
    if (tid < H_DIM) {
        float m = -1e30f;
        for (int h = 0; h < H_DIM; h++) m = fmaxf(m, slog[h]);
        float sum = 0.f;
        for (int h = 0; h < H_DIM; h++) sum += expf(slog[h] - m);
        g_gate[b * H_DIM + tid] = expf(slog[tid] - m) / sum;
    }
    for (int i = tid; i < P_DIM * HIN; i += 128) {
        int p = i / HIN, k = i % HIN;
        float v = (k < FEAT) ? sfe[k] : embeds[p * EMB + (k - FEAT)];
        g_hin[(p * B_DIM + b) * HIN + k] = v;
    }
}

// ---------------- kB: hmid = relu(hin @ gen_W1^T + gen_b1) ---------------
__global__ void kB(const float* __restrict__ W1,
                   const float* __restrict__ b1) {
    int idx = blockIdx.x * blockDim.x + threadIdx.x;    // 32 x 256
    int h = idx >> 10, r = idx & 1023, pb = r >> 5, j = r & 31;
    const float4* w = (const float4*)(W1 + (size_t)(h * GH + j) * HIN);
    const float4* hv = (const float4*)(g_hin + pb * HIN);
    float s = 0.f;
#pragma unroll
    for (int i = 0; i < HIN / 4; i++) {
        float4 a = hv[i], ww = w[i];
        s += a.x * ww.x + a.y * ww.y + a.z * ww.z + a.w * ww.w;
    }
    s += b1[h * GH + j];
    g_hmid[(h * PB + pb) * GH + j] = fmaxf(s, 0.f);
}

// ---------------- stage att weight tile (tile,h) via cp.async ------------
static __device__ __forceinline__ void stage_att(
    float* abuf, int tile, int h, int tid,
    const float* __restrict__ attW) {
    const int t0 = tile * TILE_T;
    const int nrow = min(TILE_T, T_DIM - t0);
    const unsigned uA = smem_u32(abuf);
    const float4* srcA = (const float4*)(attW + (size_t)(h * T_DIM + t0) * HIN);
    if (nrow == TILE_T) {
#pragma unroll
        for (int it = 0; it < 12; ++it) {               // 64*24 = 1536 f4
            int i = tid + it * 128;
            int r = i / (HIN / 4), c = i % (HIN / 4);
            CP16(uA + (unsigned)(r * ATT_STRIDE + c * 4) * 4u, srcA + i);
        }
    } else {
        int nA = nrow * (HIN / 4);
#pragma unroll
        for (int it = 0; it < 12; ++it) {
            int i = tid + it * 128;
            if (i < nA) {
                int r = i / (HIN / 4), c = i % (HIN / 4);
                CP16(uA + (unsigned)(r * ATT_STRIDE + c * 4) * 4u, srcA + i);
            }
        }
    }
}

// ---------------- stage gen+hmid (tile,h) into gen buffer ----------------
static __device__ __forceinline__ void stage_gen(
    float* gbuf, int tile, int h, int tid,
    const float* __restrict__ genW2) {
    const int t0 = tile * TILE_T;
    const int nrow = min(TILE_T, T_DIM - t0);
    const unsigned uG = smem_u32(gbuf);
    const unsigned uM = smem_u32(gbuf + OFF_HMID);
    const float4* srcG = (const float4*)(genW2 + (size_t)(h * T_DIM + t0) * GH);
    const float4* srcM = (const float4*)(g_hmid + h * PB * GH);
    CP16(uM + (unsigned)tid * 16u, srcM + tid);
    CP16(uM + (unsigned)(tid + 128) * 16u, srcM + tid + 128);
    if (nrow == TILE_T) {
#pragma unroll
        for (int it = 0; it < 4; ++it) {                // 64*8 = 512 f4
            int i = tid + it * 128;
            int r = i >> 3, c = i & 7;
            CP16(uG + (unsigned)(r * GEN_STRIDE + c * 4) * 4u, srcG + i);
        }
    } else {
        int nG = nrow * (GH / 4);
#pragma unroll
        for (int it = 0; it < 4; ++it) {
            int i = tid + it * 128;
            if (i < nG) {
                int r = i >> 3, c = i & 7;
                CP16(uG + (unsigned)(r * GEN_STRIDE + c * 4) * 4u, srcG + i);
            }
        }
    }
}

// ---------------- main fused kernel --------------------------------------
// 128 threads = 32 t-lanes x 4 pb-groups; thread owns 2 t x 8 pb.
// att double-buffered (prefetch at top); gen single-buffered (re-staged at
// mid sync); biases + gate via broadcast LDG. 3 blocks/SM = 12 warps.
__global__ __launch_bounds__(128, 3) void k_main(
    const float* __restrict__ attW, const float* __restrict__ attB,
    const float* __restrict__ genW2, const float* __restrict__ genB2,
    float* __restrict__ out) {
    extern __shared__ float smem[];
    float* abufs[2] = { smem, smem + ABUF_FLOATS };
    float* gbuf  = smem + 2 * ABUF_FLOATS;
    float* sHin  = gbuf + GBUF_FLOATS;                   // 32*96 = 3072

    const int tid = threadIdx.x;
    const int lane = tid & 31;                           // t-lane
    const int wpb = tid >> 5;                            // pb group 0..3
    const int bid = blockIdx.x;

    for (int i = tid; i < PB * HIN; i += 128) sHin[i] = g_hin[i];

    const int ntile = (NUM_TILES - bid + GRID_MAIN - 1) / GRID_MAIN;
    const int nit = ntile * H_DIM;

    stage_att(abufs[0], bid, 0, tid, attW);
    stage_gen(gbuf, bid, 0, tid, genW2);
    CP_COMMIT();

    float comb[JT][8];

    for (int it = 0; it < nit; ++it) {
        const int cur = it & 1;
        const int h = it & 7;
        const int tile = bid + (it >> 3) * GRID_MAIN;
        const int t0 = tile * TILE_T;

        CP_WAIT0();
        __syncthreads();    // current att+gen landed; prev iter fully done

        // bias + gate loads early (broadcast/coalesced LDG, land before use)
        float gb[JT], ab[JT];
#pragma unroll
        for (int jt = 0; jt < JT; ++jt) {
            int t = t0 + lane + 32 * jt;
            bool v = t < T_DIM;
            gb[jt] = v ? __ldg(genB2 + (size_t)h * T_DIM + t) : 0.f;
            ab[jt] = v ? __ldg(attB + (size_t)h * T_DIM + t) : 0.f;
        }
        float4 gt0 = __ldg((const float4*)(g_gate + h * B_DIM));      // gate[h][0..3]
        float4 gt1 = __ldg((const float4*)(g_gate + h * B_DIM) + 1);  // gate[h][4..7]

        // prefetch next att NOW -> full iteration to land
        if (it + 1 < nit) {
            const int n2 = it + 1;
            stage_att(abufs[cur ^ 1], bid + (n2 >> 3) * GRID_MAIN, n2 & 7,
                      tid, attW);
        }
        CP_COMMIT();

        const float* sAtt  = abufs[cur];
        const float* sGen  = gbuf;
        const float* sHmid = gbuf + OFF_HMID;

        if (h == 0) {
#pragma unroll
            for (int jt = 0; jt < JT; ++jt)
#pragma unroll
                for (int j = 0; j < 8; ++j) comb[jt][j] = 0.f;
        }

        unsigned long long acc[JT][8];
#pragma unroll
        for (int jt = 0; jt < JT; ++jt)
#pragma unroll
            for (int j = 0; j < 8; ++j) acc[jt][j] = 0ull;

        // ---------- gen GEMM: hmid[h,pb,:] . genW2[h,t,:] ----------
#pragma unroll
        for (int k4 = 0; k4 < GH / 4; ++k4) {
            ulonglong2 w[JT];
#pragma unroll
            for (int jt = 0; jt < JT; ++jt)
                w[jt] = *(const ulonglong2*)&sGen[(lane + 32 * jt) * GEN_STRIDE + k4 * 4];
#pragma unroll
            for (int j = 0; j < 8; ++j) {
                ulonglong2 hv = *(const ulonglong2*)&sHmid[(wpb * 8 + j) * GH + k4 * 4];
#pragma unroll
                for (int jt = 0; jt < JT; ++jt) {
                    acc[jt][j] = ffma2(hv.x, w[jt].x, acc[jt][j]);
                    acc[jt][j] = ffma2(hv.y, w[jt].y, acc[jt][j]);
                }
            }
        }
        float gv[JT][8];
#pragma unroll
        for (int jt = 0; jt < JT; ++jt)
#pragma unroll
            for (int j = 0; j < 8; ++j) {
                float2 f = upk(acc[jt][j]);
                gv[jt][j] = f.x + f.y + gb[jt];
                acc[jt][j] = 0ull;
            }

        __syncthreads();    // everyone done reading gen buffer
        if (it + 1 < nit) { // prefetch next gen while att GEMM runs
            const int n2 = it + 1;
            stage_gen(gbuf, bid + (n2 >> 3) * GRID_MAIN, n2 & 7, tid, genW2);
        }
        CP_COMMIT();

        // ---------- att GEMM: hin[pb,:] . attW[h,t,:] ----------
#pragma unroll 4
        for (int k4 = 0; k4 < HIN / 4; ++k4) {
            ulonglong2 w[JT];
#pragma unroll
            for (int jt = 0; jt < JT; ++jt)
                w[jt] = *(const ulonglong2*)&sAtt[(lane + 32 * jt) * ATT_STRIDE + k4 * 4];
#pragma unroll
            for (int j = 0; j < 8; ++j) {
                ulonglong2 hv = *(const ulonglong2*)&sHin[(wpb * 8 + j) * HIN + k4 * 4];
#pragma unroll
                for (int jt = 0; jt < JT; ++jt) {
                    acc[jt][j] = ffma2(hv.x, w[jt].x, acc[jt][j]);
                    acc[jt][j] = ffma2(hv.y, w[jt].y, acc[jt][j]);
                }
            }
        }

        // ---------- sigmoid + gated combine: gate[h, b], b = j ----------
        float gt[8] = { gt0.x, gt0.y, gt0.z, gt0.w, gt1.x, gt1.y, gt1.z, gt1.w };
#pragma unroll
        for (int jt = 0; jt < JT; ++jt)
#pragma unroll
            for (int j = 0; j < 8; ++j) {
                float2 f = upk(acc[jt][j]);
                float a = f.x + f.y + ab[jt];
                float imp = 1.0f / (1.0f + __expf(-a));
                comb[jt][j] = fmaf(gt[j] * gv[jt][j], imp, comb[jt][j]);
            }

        // ---------- store at last head (coalesced over lanes) ----------
        if (h == 7) {
#pragma unroll
            for (int jt = 0; jt < JT; ++jt) {
                int t = t0 + lane + 32 * jt;
                if (t < T_DIM) {
#pragma unroll
                    for (int j = 0; j < 8; ++j)
                        out[(size_t)(j * P_DIM + wpb) * T_DIM + t] = comb[jt][j];
                }
            }
        }
    }
}

// ---------------- launch ----------------
extern "C" void kernel_launch(void* const* d_in, const int* in_sizes, int n_in,
                              void* d_out, int out_size) {
    const float* x      = (const float*)d_in[0];
    const float* fe_W1  = (const float*)d_in[1];
    const float* fe_b1  = (const float*)d_in[2];
    const float* fe_W2  = (const float*)d_in[3];
    const float* fe_b2  = (const float*)d_in[4];
    const float* embeds = (const float*)d_in[5];
    const float* gen_W1 = (const float*)d_in[6];
    const float* gen_b1 = (const float*)d_in[7];
    const float* gen_W2 = (const float*)d_in[8];
    const float* gen_b2 = (const float*)d_in[9];
    const float* att_W  = (const float*)d_in[10];
    const float* att_b  = (const float*)d_in[11];
    const float* gate_W = (const float*)d_in[12];
    const float* gate_b = (const float*)d_in[13];
    float* out = (float*)d_out;

    size_t smem = (size_t)(2 * ABUF_FLOATS + GBUF_FLOATS + PB * HIN) * sizeof(float);
    cudaFuncSetAttribute(k_main, cudaFuncAttributeMaxDynamicSharedMemorySize, (int)smem);

    kA1<<<64, 128>>>(x, fe_W1, fe_b1);
    kA2<<<B_DIM, 128>>>(fe_W2, fe_b2, embeds, gate_W, gate_b);
    kB<<<32, 256>>>(gen_W1, gen_b1);
    k_main<<<GRID_MAIN, 128, smem>>>(att_W, att_b, gen_W2, gen_b2, out);
}